// round 3
// baseline (speedup 1.0000x reference)
#include <cuda_runtime.h>
#include <math_constants.h>

#define ROWLEN 8192
#define NROWS  4096
#define K      8
#define THREADS 256
#define NWARP  (THREADS / 32)
#define NF4    (ROWLEN / 4 / THREADS)   // 8 float4 per thread
#define CAP    512

// Order-preserving map: float -> uint32 (f1 > f2 <=> u1 > u2).
__device__ __forceinline__ unsigned fflip(float f) {
    unsigned u = __float_as_uint(f);
    return (u & 0x80000000u) ? ~u : (u | 0x80000000u);
}
__device__ __forceinline__ float funflip(unsigned u) {
    return __uint_as_float((u & 0x80000000u) ? (u ^ 0x80000000u) : ~u);
}
__device__ __forceinline__ unsigned long long mkkey(float f, int idx) {
    // tie-break: smaller index wins -> complement index in low bits
    return ((unsigned long long)fflip(f) << 32) | (unsigned)(ROWLEN - 1 - idx);
}

// Branchy insert into a register-resident sorted-descending top-8.
__device__ __forceinline__ void insert8(unsigned long long (&t)[K],
                                        unsigned long long key) {
    if (key > t[K - 1]) {
        t[K - 1] = key;
#pragma unroll
        for (int s = K - 1; s > 0; s--) {
            unsigned long long a = t[s - 1], b = t[s];
            t[s - 1] = a > b ? a : b;
            t[s]     = a > b ? b : a;
        }
    }
}

// Bitonic top-8 merge of two sorted-desc 8-lists in smem: dst <- top8(dst, src).
__device__ __forceinline__ void merge8(unsigned long long* dst,
                                       const unsigned long long* src) {
    unsigned long long m[K];
#pragma unroll
    for (int j = 0; j < K; j++) {
        unsigned long long a = dst[j], b = src[K - 1 - j];
        m[j] = a > b ? a : b;           // top-8 multiset, bitonic
    }
#pragma unroll
    for (int d = K / 2; d >= 1; d >>= 1) {
#pragma unroll
        for (int j = 0; j < K; j++) {
            if ((j & d) == 0) {
                unsigned long long lo = m[j], hi = m[j | d];
                m[j]     = lo > hi ? lo : hi;
                m[j | d] = lo > hi ? hi : lo;
            }
        }
    }
#pragma unroll
    for (int j = 0; j < K; j++) dst[j] = m[j];
}

__global__ __launch_bounds__(THREADS, 8)
void topk8_kernel(const float* __restrict__ x,
                  float* __restrict__ out_vals,
                  float* __restrict__ out_idx) {
    // Group maxes (hot path) and merge lists (later phases) have disjoint
    // lifetimes -> union. 16 KB.
    __shared__ union {
        float              m[NF4 * THREADS];     // 8 KB, pass1/pass2
        unsigned long long list[THREADS * K];    // 16 KB, reduction/fallback
    } sb;
    __shared__ unsigned long long s_cand[CAP];   // 4 KB
    __shared__ float s_bound[NWARP];
    __shared__ float s_t8;
    __shared__ int   s_count;

    const int row  = blockIdx.x;
    const int tid  = threadIdx.x;
    const int warp = tid >> 5;
    const int lane = tid & 31;
    const float4* __restrict__ p =
        reinterpret_cast<const float4*>(x + (size_t)row * ROWLEN);

    // ---- pass 1: stream row, group maxes -> smem, thread max -> reg ----
    float tmax = -CUDART_INF_F;
#pragma unroll
    for (int i = 0; i < NF4; i++) {
        float4 v = p[tid + i * THREADS];
        float mi = fmaxf(fmaxf(v.x, v.y), fmaxf(v.z, v.w));
        sb.m[i * THREADS + tid] = mi;
        tmax = fmaxf(tmax, mi);
    }

    // ---- safe threshold: 8th largest of each warp's 32 thread-maxes ----
    float s = tmax;
#pragma unroll
    for (int k = 2; k <= 32; k <<= 1) {
#pragma unroll
        for (int j = k >> 1; j > 0; j >>= 1) {
            float o = __shfl_xor_sync(0xffffffffu, s, j);
            bool dir_asc = ((lane & k) == 0);
            bool lower   = ((lane & j) == 0);
            s = (dir_asc != lower) ? fmaxf(s, o) : fminf(s, o);
        }
    }
    float wbound = __shfl_sync(0xffffffffu, s, 24);  // ascending: idx24 = 8th largest
    if (lane == 0) s_bound[warp] = wbound;
    __syncthreads();

    if (tid == 0) {
        float t = s_bound[0];
#pragma unroll
        for (int w = 1; w < NWARP; w++) t = fmaxf(t, s_bound[w]);
        s_t8 = t;          // each warp bound <= true row 8th-largest (subset)
        s_count = 0;
    }
    __syncthreads();
    const float t8 = s_t8;

    // ---- pass 2: reload ONLY surviving groups (L1/L2 hits, rare) ----
#pragma unroll
    for (int i = 0; i < NF4; i++) {
        if (sb.m[i * THREADS + tid] >= t8) {         // rare
            float4 v = p[tid + i * THREADS];
            const int base = (tid + i * THREADS) * 4;
            if (v.x >= t8) { int q = atomicAdd(&s_count, 1); if (q < CAP) s_cand[q] = mkkey(v.x, base + 0); }
            if (v.y >= t8) { int q = atomicAdd(&s_count, 1); if (q < CAP) s_cand[q] = mkkey(v.y, base + 1); }
            if (v.z >= t8) { int q = atomicAdd(&s_count, 1); if (q < CAP) s_cand[q] = mkkey(v.z, base + 2); }
            if (v.w >= t8) { int q = atomicAdd(&s_count, 1); if (q < CAP) s_cand[q] = mkkey(v.w, base + 3); }
        }
    }
    __syncthreads();       // after this, sb.m is dead -> sb.list usable
    const int C = s_count; // C >= 8 guaranteed

    if (C <= CAP) {
        // ---- warp 0 reduces candidates (uniform branch: C is block-uniform) ----
        if (warp == 0) {
            unsigned long long top[K];
#pragma unroll
            for (int j = 0; j < K; j++) top[j] = 0ULL;
            for (int c = lane; c < C; c += 32) insert8(top, s_cand[c]);
#pragma unroll
            for (int j = 0; j < K; j++) sb.list[lane * K + j] = top[j];
            __syncwarp();
            for (int stride = 16; stride >= 1; stride >>= 1) {
                if (lane < stride)
                    merge8(&sb.list[lane * K], &sb.list[(lane + stride) * K]);
                __syncwarp();
            }
            if (lane < K) {
                unsigned long long key = sb.list[lane];
                out_vals[(size_t)row * K + lane] = funflip((unsigned)(key >> 32));
                out_idx [(size_t)row * K + lane] =
                    (float)(ROWLEN - 1 - (unsigned)(key & 0xFFFFFFFFu));
            }
        }
    } else {
        // ---- exact fallback: reload everything, per-thread top-8, tree merge ----
        unsigned long long top[K];
#pragma unroll
        for (int j = 0; j < K; j++) top[j] = 0ULL;
#pragma unroll
        for (int i = 0; i < NF4; i++) {
            float4 v = p[tid + i * THREADS];
            const int base = (tid + i * THREADS) * 4;
            insert8(top, mkkey(v.x, base + 0));
            insert8(top, mkkey(v.y, base + 1));
            insert8(top, mkkey(v.z, base + 2));
            insert8(top, mkkey(v.w, base + 3));
        }
#pragma unroll
        for (int j = 0; j < K; j++) sb.list[tid * K + j] = top[j];
        for (int stride = THREADS / 2; stride >= 1; stride >>= 1) {
            __syncthreads();
            if (tid < stride)
                merge8(&sb.list[tid * K], &sb.list[(tid + stride) * K]);
        }
        __syncthreads();
        if (tid < K) {
            unsigned long long key = sb.list[tid];
            out_vals[(size_t)row * K + tid] = funflip((unsigned)(key >> 32));
            out_idx [(size_t)row * K + tid] =
                (float)(ROWLEN - 1 - (unsigned)(key & 0xFFFFFFFFu));
        }
    }
}

extern "C" void kernel_launch(void* const* d_in, const int* in_sizes, int n_in,
                              void* d_out, int out_size) {
    const float* x = (const float*)d_in[0];
    float* out_vals = (float*)d_out;
    float* out_idx  = out_vals + (size_t)NROWS * K;
    topk8_kernel<<<NROWS, THREADS>>>(x, out_vals, out_idx);
}

// round 4
// speedup vs baseline: 1.0054x; 1.0054x over previous
#include <cuda_runtime.h>
#include <math_constants.h>

#define ROWLEN 8192
#define NROWS  4096
#define K      8
#define THREADS 256
#define NWARP  (THREADS / 32)
#define NF4    (ROWLEN / 4 / THREADS)   // 8 float4 per thread
#define CAP    512

// Order-preserving map: float -> uint32 (f1 > f2 <=> u1 > u2).
__device__ __forceinline__ unsigned fflip(float f) {
    unsigned u = __float_as_uint(f);
    return (u & 0x80000000u) ? ~u : (u | 0x80000000u);
}
__device__ __forceinline__ float funflip(unsigned u) {
    return __uint_as_float((u & 0x80000000u) ? (u ^ 0x80000000u) : ~u);
}
__device__ __forceinline__ unsigned long long mkkey(float f, int idx) {
    // tie-break: smaller index wins -> complement index in low bits
    return ((unsigned long long)fflip(f) << 32) | (unsigned)(ROWLEN - 1 - idx);
}

// Branchy insert into a register-resident sorted-descending top-8.
__device__ __forceinline__ void insert8(unsigned long long (&t)[K],
                                        unsigned long long key) {
    if (key > t[K - 1]) {
        t[K - 1] = key;
#pragma unroll
        for (int s = K - 1; s > 0; s--) {
            unsigned long long a = t[s - 1], b = t[s];
            t[s - 1] = a > b ? a : b;
            t[s]     = a > b ? b : a;
        }
    }
}

// Bitonic top-8 merge of two sorted-desc 8-lists in smem: dst <- top8(dst, src).
__device__ __forceinline__ void merge8(unsigned long long* dst,
                                       const unsigned long long* src) {
    unsigned long long m[K];
#pragma unroll
    for (int j = 0; j < K; j++) {
        unsigned long long a = dst[j], b = src[K - 1 - j];
        m[j] = a > b ? a : b;           // top-8 multiset, bitonic
    }
#pragma unroll
    for (int d = K / 2; d >= 1; d >>= 1) {
#pragma unroll
        for (int j = 0; j < K; j++) {
            if ((j & d) == 0) {
                unsigned long long lo = m[j], hi = m[j | d];
                m[j]     = lo > hi ? lo : hi;
                m[j | d] = lo > hi ? hi : lo;
            }
        }
    }
#pragma unroll
    for (int j = 0; j < K; j++) dst[j] = m[j];
}

__global__ __launch_bounds__(THREADS, 8)
void topk8_kernel(const float* __restrict__ x,
                  float* __restrict__ out_vals,
                  float* __restrict__ out_idx) {
    // Group maxes (hot path) and merge lists (later phases) have disjoint
    // lifetimes -> union. 16 KB.
    __shared__ union {
        float              m[NF4 * THREADS];     // 8 KB, pass1/pass2
        unsigned long long list[THREADS * K];    // 16 KB, reduction/fallback
    } sb;
    __shared__ unsigned long long s_cand[CAP];   // 4 KB
    __shared__ float s_bound[NWARP];
    __shared__ float s_t8;
    __shared__ int   s_count;

    const int row  = blockIdx.x;
    const int tid  = threadIdx.x;
    const int warp = tid >> 5;
    const int lane = tid & 31;
    const float4* __restrict__ p =
        reinterpret_cast<const float4*>(x + (size_t)row * ROWLEN);

    // ---- pass 1: stream row, group maxes -> smem, thread max -> reg ----
    float tmax = -CUDART_INF_F;
#pragma unroll
    for (int i = 0; i < NF4; i++) {
        float4 v = p[tid + i * THREADS];
        float mi = fmaxf(fmaxf(v.x, v.y), fmaxf(v.z, v.w));
        sb.m[i * THREADS + tid] = mi;
        tmax = fmaxf(tmax, mi);
    }

    // ---- safe threshold: 8th largest of each warp's 32 thread-maxes ----
    float s = tmax;
#pragma unroll
    for (int k = 2; k <= 32; k <<= 1) {
#pragma unroll
        for (int j = k >> 1; j > 0; j >>= 1) {
            float o = __shfl_xor_sync(0xffffffffu, s, j);
            bool dir_asc = ((lane & k) == 0);
            bool lower   = ((lane & j) == 0);
            s = (dir_asc != lower) ? fmaxf(s, o) : fminf(s, o);
        }
    }
    float wbound = __shfl_sync(0xffffffffu, s, 24);  // ascending: idx24 = 8th largest
    if (lane == 0) s_bound[warp] = wbound;
    __syncthreads();

    if (tid == 0) {
        float t = s_bound[0];
#pragma unroll
        for (int w = 1; w < NWARP; w++) t = fmaxf(t, s_bound[w]);
        s_t8 = t;          // each warp bound <= true row 8th-largest (subset)
        s_count = 0;
    }
    __syncthreads();
    const float t8 = s_t8;

    // ---- pass 2: reload ONLY surviving groups (L1/L2 hits, rare) ----
#pragma unroll
    for (int i = 0; i < NF4; i++) {
        if (sb.m[i * THREADS + tid] >= t8) {         // rare
            float4 v = p[tid + i * THREADS];
            const int base = (tid + i * THREADS) * 4;
            if (v.x >= t8) { int q = atomicAdd(&s_count, 1); if (q < CAP) s_cand[q] = mkkey(v.x, base + 0); }
            if (v.y >= t8) { int q = atomicAdd(&s_count, 1); if (q < CAP) s_cand[q] = mkkey(v.y, base + 1); }
            if (v.z >= t8) { int q = atomicAdd(&s_count, 1); if (q < CAP) s_cand[q] = mkkey(v.z, base + 2); }
            if (v.w >= t8) { int q = atomicAdd(&s_count, 1); if (q < CAP) s_cand[q] = mkkey(v.w, base + 3); }
        }
    }
    __syncthreads();       // after this, sb.m is dead -> sb.list usable
    const int C = s_count; // C >= 8 guaranteed

    if (C <= CAP) {
        // ---- warp 0 reduces candidates (uniform branch: C is block-uniform) ----
        if (warp == 0) {
            unsigned long long top[K];
#pragma unroll
            for (int j = 0; j < K; j++) top[j] = 0ULL;
            for (int c = lane; c < C; c += 32) insert8(top, s_cand[c]);
#pragma unroll
            for (int j = 0; j < K; j++) sb.list[lane * K + j] = top[j];
            __syncwarp();
            for (int stride = 16; stride >= 1; stride >>= 1) {
                if (lane < stride)
                    merge8(&sb.list[lane * K], &sb.list[(lane + stride) * K]);
                __syncwarp();
            }
            if (lane < K) {
                unsigned long long key = sb.list[lane];
                out_vals[(size_t)row * K + lane] = funflip((unsigned)(key >> 32));
                out_idx [(size_t)row * K + lane] =
                    (float)(ROWLEN - 1 - (unsigned)(key & 0xFFFFFFFFu));
            }
        }
    } else {
        // ---- exact fallback: reload everything, per-thread top-8, tree merge ----
        unsigned long long top[K];
#pragma unroll
        for (int j = 0; j < K; j++) top[j] = 0ULL;
#pragma unroll
        for (int i = 0; i < NF4; i++) {
            float4 v = p[tid + i * THREADS];
            const int base = (tid + i * THREADS) * 4;
            insert8(top, mkkey(v.x, base + 0));
            insert8(top, mkkey(v.y, base + 1));
            insert8(top, mkkey(v.z, base + 2));
            insert8(top, mkkey(v.w, base + 3));
        }
#pragma unroll
        for (int j = 0; j < K; j++) sb.list[tid * K + j] = top[j];
        for (int stride = THREADS / 2; stride >= 1; stride >>= 1) {
            __syncthreads();
            if (tid < stride)
                merge8(&sb.list[tid * K], &sb.list[(tid + stride) * K]);
        }
        __syncthreads();
        if (tid < K) {
            unsigned long long key = sb.list[tid];
            out_vals[(size_t)row * K + tid] = funflip((unsigned)(key >> 32));
            out_idx [(size_t)row * K + tid] =
                (float)(ROWLEN - 1 - (unsigned)(key & 0xFFFFFFFFu));
        }
    }
}

extern "C" void kernel_launch(void* const* d_in, const int* in_sizes, int n_in,
                              void* d_out, int out_size) {
    const float* x = (const float*)d_in[0];
    float* out_vals = (float*)d_out;
    float* out_idx  = out_vals + (size_t)NROWS * K;
    topk8_kernel<<<NROWS, THREADS>>>(x, out_vals, out_idx);
}